// round 12
// baseline (speedup 1.0000x reference)
#include <cuda_runtime.h>

// Problem shapes (fixed by the dataset)
#define NB 16        // batch
#define NC 3         // channels
#define TH 512       // tex H
#define TW 512       // tex W
#define OH 768       // out H
#define OW 768       // out W
#define NI 25        // lut dim 0 (part index)
#define LD 256       // lut dims 1,2
#define TD 25        // table coverage for vi/ui (data has values in [0,25))

#define TEX_PLANE (TH*TW)          // 262144
#define TEX_IMG   (NC*TEX_PLANE)   // 786432
#define OUT_PLANE (OH*OW)          // 589824
#define OUT_IMG   (NC*OUT_PLANE)   // 1769472
#define TBL_PER_B (NI*TD*TD)       // 15625
#define PSTRIDE   15628            // TBL_PER_B padded to /4 for float4 copies

#define CTAS_PER_B 9               // 589824 = 9 * 65536 -> 144 CTAs = one wave
#define QUADS_PER_CTA 16384        // 65536 pixels / 4
#define MAP_THREADS 1024

// Precomputed sample table, SoA: 3 planes of [B][PSTRIDE] floats (~3 MB, L2-resident)
__device__ float g_tab[3][NB * PSTRIDE];

// tex transposed to interleaved RGBX (float4 per pixel, 64 MB).
// One LDG.128 fetches all 3 channels of a texel.
__device__ float4 g_tex4[NB * TEX_PLANE];

// ---------------------------------------------------------------------------
// Kernel 0: transpose tex [B][C][H][W] -> g_tex4 [B][H][W][rgbx].
// Pure streaming: 3 coalesced plane reads + 1 coalesced float4 write.
#define TP_THREADS 256
__global__ void __launch_bounds__(TP_THREADS)
transpose_tex(const float* __restrict__ tex) {
    int p = blockIdx.x * blockDim.x + threadIdx.x;   // pixel id in [0, NB*TEX_PLANE)
    if (p >= NB * TEX_PLANE) return;
    int b   = p / TEX_PLANE;
    int off = p - b * TEX_PLANE;
    const float* __restrict__ base = tex + (size_t)b * TEX_IMG;
    float r = base[off];
    float g = base[TEX_PLANE + off];
    float bl = base[2 * TEX_PLANE + off];
    g_tex4[p] = make_float4(r, g, bl, 0.0f);
}

// ---------------------------------------------------------------------------
// Variant A (map_pixels' fallback — branchy, exact R4/R9/R11 form):
// bilinear grid-sample matching torch grid_sample (bilinear, zeros,
// align_corners=True).
__device__ __forceinline__ float3 sample_tex_branchy(const float* __restrict__ tex,
                                                     int b, float us, float vs) {
    float uI = us * 2.0f - 1.0f;
    float vI = (1.0f - vs) * 2.0f - 1.0f;
    float x = (uI + 1.0f) * 0.5f * (float)(TW - 1);
    float y = (vI + 1.0f) * 0.5f * (float)(TH - 1);
    float x0f = floorf(x);
    float y0f = floorf(y);
    float wx = x - x0f;
    float wy = y - y0f;
    int x0 = (int)x0f;
    int y0 = (int)y0f;

    const float* __restrict__ base = tex + (size_t)b * TEX_IMG;
    float r = 0.0f, g = 0.0f, bl = 0.0f;
#pragma unroll
    for (int dy = 0; dy < 2; dy++) {
#pragma unroll
        for (int dx = 0; dx < 2; dx++) {
            int xx = x0 + dx;
            int yy = y0 + dy;
            bool valid = (xx >= 0) & (xx < TW) & (yy >= 0) & (yy < TH);
            float w = (dy ? wy : (1.0f - wy)) * (dx ? wx : (1.0f - wx));
            if (valid) {
                int off = yy * TW + xx;
                r  += __ldg(base + off) * w;
                g  += __ldg(base + TEX_PLANE + off) * w;
                bl += __ldg(base + 2 * TEX_PLANE + off) * w;
            }
        }
    }
    return make_float3(r, g, bl);
}

// Variant B (build_table — branchless, gathers from interleaved g_tex4):
// ONE LDG.128 per corner (4 loads/entry instead of 12). Loads always issue
// from clamped addresses; validity folded into the weight.
__device__ __forceinline__ float3 sample_tex4_nobranch(int b, float us, float vs) {
    float uI = us * 2.0f - 1.0f;
    float vI = (1.0f - vs) * 2.0f - 1.0f;
    float x = (uI + 1.0f) * 0.5f * (float)(TW - 1);
    float y = (vI + 1.0f) * 0.5f * (float)(TH - 1);
    float x0f = floorf(x);
    float y0f = floorf(y);
    float wx = x - x0f;
    float wy = y - y0f;
    int x0 = (int)x0f;
    int y0 = (int)y0f;

    const float4* __restrict__ base = g_tex4 + (size_t)b * TEX_PLANE;

    float4 tc[4];
    float wq[4];
#pragma unroll
    for (int dy = 0; dy < 2; dy++) {
#pragma unroll
        for (int dx = 0; dx < 2; dx++) {
            int k = dy * 2 + dx;
            int xx = x0 + dx;
            int yy = y0 + dy;
            bool valid = (xx >= 0) & (xx < TW) & (yy >= 0) & (yy < TH);
            float w = (dy ? wy : (1.0f - wy)) * (dx ? wx : (1.0f - wx));
            wq[k] = valid ? w : 0.0f;
            int off = min(max(yy, 0), TH - 1) * TW + min(max(xx, 0), TW - 1);
            tc[k] = __ldg(base + off);
        }
    }
    float r = 0.0f, g = 0.0f, bl = 0.0f;
#pragma unroll
    for (int k = 0; k < 4; k++) {
        r  += tc[k].x * wq[k];
        g  += tc[k].y * wq[k];
        bl += tc[k].z * wq[k];
    }
    return make_float3(r, g, bl);
}

// Phase 1: build the (b, i, vi, ui) -> rgb SoA table. 4 entries per thread
// (grid-strided by quarter); 16 independent LDG.128 gathers per thread.
#define BT_THREADS 256
#define BT_QUARTER (NB * TBL_PER_B / 4)      // 62500
__global__ void __launch_bounds__(BT_THREADS)
build_table(const float* __restrict__ lut) {
    int t = blockIdx.x * blockDim.x + threadIdx.x;
    if (t >= BT_QUARTER) return;

    int eb[4], er[4];
    float us[4], vs[4];
#pragma unroll
    for (int h = 0; h < 4; h++) {
        int e = t + h * BT_QUARTER;
        int b  = e / TBL_PER_B;
        int r  = e - b * TBL_PER_B;
        int i  = r / (TD * TD);
        int r2 = r - i * (TD * TD);
        int vi = r2 / TD;
        int ui = r2 - vi * TD;
        int lo = ((i * LD + vi) * LD + ui) * 2;
        us[h] = __ldg(lut + lo);
        vs[h] = __ldg(lut + lo + 1);
        eb[h] = b; er[h] = r;
    }
#pragma unroll
    for (int h = 0; h < 4; h++) {
        float3 c = sample_tex4_nobranch(eb[h], us[h], vs[h]);
        int o = eb[h] * PSTRIDE + er[h];
        g_tab[0][o] = c.x;
        g_tab[1][o] = c.y;
        g_tab[2][o] = c.z;
    }
}

// Phase 2: streaming pass with fp32 table slice staged in shared memory.
// 187.5 KB smem/CTA -> 1 CTA/SM, 144 CTAs = one full wave.
// Byte-identical structure to the proven R11 kernel.
__global__ void __launch_bounds__(MAP_THREADS, 1)
map_pixels(const float* __restrict__ tex,
           const int* __restrict__ iuv,
           const float* __restrict__ lut,
           float* __restrict__ out) {
    extern __shared__ float smem[];
    float* sr = smem;
    float* sg = smem + PSTRIDE;
    float* sb = smem + 2 * PSTRIDE;

    int b   = blockIdx.x / CTAS_PER_B;
    int sub = blockIdx.x - b * CTAS_PER_B;
    int tid = threadIdx.x;

    // Stage this batch's table slice into smem (float4 bulk copy).
#pragma unroll
    for (int c = 0; c < 3; c++) {
        const float4* src = (const float4*)&g_tab[c][b * PSTRIDE];
        float4* dst = (float4*)(smem + c * PSTRIDE);
        for (int t = tid; t < PSTRIDE / 4; t += MAP_THREADS)
            dst[t] = src[t];
    }
    __syncthreads();

    const int* __restrict__ ib = iuv + (size_t)b * OUT_IMG;
    float* __restrict__ ob = out + (size_t)b * OUT_IMG;
    const int q0 = sub * QUADS_PER_CTA;

    // 2 quads (8 pixels) per iteration: 6 front-batched int4 loads for MLP.
#pragma unroll
    for (int j = 0; j < QUADS_PER_CTA / (2 * MAP_THREADS); j++) {
        int qa = q0 + j * (2 * MAP_THREADS) + tid;
        int qb = qa + MAP_THREADS;

        int4 iA = ((const int4*)(ib))[qa];
        int4 iB = ((const int4*)(ib))[qb];
        int4 uA = ((const int4*)(ib + OUT_PLANE))[qa];
        int4 uB = ((const int4*)(ib + OUT_PLANE))[qb];
        int4 vA = ((const int4*)(ib + 2 * OUT_PLANE))[qa];
        int4 vB = ((const int4*)(ib + 2 * OUT_PLANE))[qb];

        int ia[8] = {iA.x, iA.y, iA.z, iA.w, iB.x, iB.y, iB.z, iB.w};
        int ua[8] = {uA.x, uA.y, uA.z, uA.w, uB.x, uB.y, uB.z, uB.w};
        int va[8] = {vA.x, vA.y, vA.z, vA.w, vB.x, vB.y, vB.z, vB.w};

        // Compute all 8 table indices + a combined fast-path predicate.
        // For int32 inputs, rint(clip(ua/255,0,1)*255) == clamp(ua,0,255).
        int idx[8];
        bool fast = true;
#pragma unroll
        for (int k = 0; k < 8; k++) {
            int i  = min(max(ia[k], 0), NI - 1);
            int ui = min(max(ua[k], 0), LD - 1);
            int vi = min(max(va[k], 0), LD - 1);
            fast = fast & (ui < TD) & (vi < TD);
            int uic = min(ui, TD - 1);
            int vic = min(vi, TD - 1);
            idx[k] = (i * TD + vic) * TD + uic;
        }

        float rr[8], gg[8], bb[8];
        if (fast) {
            // Straight-line: 24 independent LDS, batched by ptxas.
#pragma unroll
            for (int k = 0; k < 8; k++) rr[k] = sr[idx[k]];
#pragma unroll
            for (int k = 0; k < 8; k++) gg[k] = sg[idx[k]];
#pragma unroll
            for (int k = 0; k < 8; k++) bb[k] = sb[idx[k]];
        } else {
            // Cold mixed path: per-pixel, exact reference semantics.
#pragma unroll
            for (int k = 0; k < 8; k++) {
                int i  = min(max(ia[k], 0), NI - 1);
                int ui = min(max(ua[k], 0), LD - 1);
                int vi = min(max(va[k], 0), LD - 1);
                if (ui < TD && vi < TD) {
                    int id = (i * TD + vi) * TD + ui;
                    rr[k] = sr[id]; gg[k] = sg[id]; bb[k] = sb[id];
                } else {
                    int lo = ((i * LD + vi) * LD + ui) * 2;
                    float3 c = sample_tex_branchy(tex, b, lut[lo], lut[lo + 1]);
                    rr[k] = c.x; gg[k] = c.y; bb[k] = c.z;
                }
            }
        }

        ((float4*)(ob))[qa]                 = make_float4(rr[0], rr[1], rr[2], rr[3]);
        ((float4*)(ob))[qb]                 = make_float4(rr[4], rr[5], rr[6], rr[7]);
        ((float4*)(ob + OUT_PLANE))[qa]     = make_float4(gg[0], gg[1], gg[2], gg[3]);
        ((float4*)(ob + OUT_PLANE))[qb]     = make_float4(gg[4], gg[5], gg[6], gg[7]);
        ((float4*)(ob + 2 * OUT_PLANE))[qa] = make_float4(bb[0], bb[1], bb[2], bb[3]);
        ((float4*)(ob + 2 * OUT_PLANE))[qb] = make_float4(bb[4], bb[5], bb[6], bb[7]);
    }
}

extern "C" void kernel_launch(void* const* d_in, const int* in_sizes, int n_in,
                              void* d_out, int out_size) {
    const float* tex = (const float*)d_in[0];   // [16,3,512,512] f32
    const int*   iuv = (const int*)d_in[1];     // [16,3,768,768] i32
    const float* lut = (const float*)d_in[2];   // [25,256,256,2] f32
    float* out = (float*)d_out;                 // [16,3,768,768] f32

    {
        int n = NB * TEX_PLANE;
        transpose_tex<<<(n + TP_THREADS - 1) / TP_THREADS, TP_THREADS>>>(tex);
    }
    build_table<<<(BT_QUARTER + BT_THREADS - 1) / BT_THREADS, BT_THREADS>>>(lut);
    {
        const int smem_bytes = 3 * PSTRIDE * (int)sizeof(float);  // 187,536 B
        // cudaFuncSetAttribute is host-side (not a stream op): capture-safe.
        cudaFuncSetAttribute(map_pixels,
                             cudaFuncAttributeMaxDynamicSharedMemorySize,
                             smem_bytes);
        map_pixels<<<NB * CTAS_PER_B, MAP_THREADS, smem_bytes>>>(tex, iuv, lut, out);
    }
}

// round 13
// speedup vs baseline: 1.3607x; 1.3607x over previous
#include <cuda_runtime.h>

// Problem shapes (fixed by the dataset)
#define NB 16        // batch
#define NC 3         // channels
#define TH 512       // tex H
#define TW 512       // tex W
#define OH 768       // out H
#define OW 768       // out W
#define NI 25        // lut dim 0 (part index)
#define LD 256       // lut dims 1,2
#define TD 25        // table coverage for vi/ui (data has values in [0,25))

#define TEX_PLANE (TH*TW)          // 262144
#define TEX_IMG   (NC*TEX_PLANE)   // 786432
#define OUT_PLANE (OH*OW)          // 589824
#define OUT_IMG   (NC*OUT_PLANE)   // 1769472
#define TBL_PER_B (NI*TD*TD)       // 15625
#define PSTRIDE   15628            // TBL_PER_B padded to /4 for float4 copies

#define CTAS_PER_B 9               // 589824 = 9 * 65536 -> 144 CTAs = one wave
#define QUADS_PER_CTA 16384        // 65536 pixels / 4
#define MAP_THREADS 1024

// Precomputed sample table, SoA: 3 planes of [B][PSTRIDE] floats (~3 MB, L2-resident)
__device__ float g_tab[3][NB * PSTRIDE];

// ---------------------------------------------------------------------------
// Variant A (map_pixels' fallback — branchy, exact R4/R9/R11 form):
// bilinear grid-sample matching torch grid_sample (bilinear, zeros,
// align_corners=True).
__device__ __forceinline__ float3 sample_tex_branchy(const float* __restrict__ tex,
                                                     int b, float us, float vs) {
    float uI = us * 2.0f - 1.0f;
    float vI = (1.0f - vs) * 2.0f - 1.0f;
    float x = (uI + 1.0f) * 0.5f * (float)(TW - 1);
    float y = (vI + 1.0f) * 0.5f * (float)(TH - 1);
    float x0f = floorf(x);
    float y0f = floorf(y);
    float wx = x - x0f;
    float wy = y - y0f;
    int x0 = (int)x0f;
    int y0 = (int)y0f;

    const float* __restrict__ base = tex + (size_t)b * TEX_IMG;
    float r = 0.0f, g = 0.0f, bl = 0.0f;
#pragma unroll
    for (int dy = 0; dy < 2; dy++) {
#pragma unroll
        for (int dx = 0; dx < 2; dx++) {
            int xx = x0 + dx;
            int yy = y0 + dy;
            bool valid = (xx >= 0) & (xx < TW) & (yy >= 0) & (yy < TH);
            float w = (dy ? wy : (1.0f - wy)) * (dx ? wx : (1.0f - wx));
            if (valid) {
                int off = yy * TW + xx;
                r  += __ldg(base + off) * w;
                g  += __ldg(base + TEX_PLANE + off) * w;
                bl += __ldg(base + 2 * TEX_PLANE + off) * w;
            }
        }
    }
    return make_float3(r, g, bl);
}

// Variant B (build_table): branchless clamped-address gather with the
// LDG.64 row-pair trick: the two x-corners of each bilinear row are adjacent
// texels, so one aligned 8-byte load at (x0 & ~1) covers both when x0 is
// even; when odd, one extra load fetches x0+1. 9 avg loads/entry vs 12.
__device__ __forceinline__ float3 sample_tex_pair(const float* __restrict__ tex,
                                                  int b, float us, float vs) {
    float uI = us * 2.0f - 1.0f;
    float vI = (1.0f - vs) * 2.0f - 1.0f;
    float x = (uI + 1.0f) * 0.5f * (float)(TW - 1);
    float y = (vI + 1.0f) * 0.5f * (float)(TH - 1);
    float x0f = floorf(x);
    float y0f = floorf(y);
    float wx = x - x0f;
    float wy = y - y0f;
    int x0 = (int)x0f;
    int y0 = (int)y0f;

    // Validity of each corner (reference: zeros padding).
    bool vx0 = (x0 >= 0) & (x0 < TW);
    bool vx1 = (x0 + 1 >= 0) & (x0 + 1 < TW);
    bool vy0 = (y0 >= 0) & (y0 < TH);
    bool vy1 = (y0 + 1 >= 0) & (y0 + 1 < TH);

    float w00 = (vy0 & vx0) ? (1.0f - wy) * (1.0f - wx) : 0.0f;
    float w01 = (vy0 & vx1) ? (1.0f - wy) * wx : 0.0f;
    float w10 = (vy1 & vx0) ? wy * (1.0f - wx) : 0.0f;
    float w11 = (vy1 & vx1) ? wy * wx : 0.0f;

    int x0c = min(max(x0, 0), TW - 1);
    int x1c = min(x0c + 1, TW - 1);
    int xe  = x0c & ~1;                 // aligned pair base, in [0, 510]
    bool odd = (x0c & 1);
    int y0c = min(max(y0, 0), TH - 1);
    int y1c = min(y0c + 1, TH - 1);

    const float* __restrict__ base = tex + (size_t)b * TEX_IMG;

    float r = 0.0f, g = 0.0f, bl = 0.0f;
#pragma unroll
    for (int c = 0; c < 3; c++) {
        const float* __restrict__ pl = base + c * TEX_PLANE;
        // Row y0: one LDG.64 + (odd ? one LDG.32 : 0)
        float2 a0 = __ldg((const float2*)(pl + y0c * TW + xe));
        float e0 = odd ? __ldg(pl + y0c * TW + x1c) : 0.0f;
        float c00 = odd ? a0.y : a0.x;
        float c01 = odd ? e0   : a0.y;
        // Row y1
        float2 a1 = __ldg((const float2*)(pl + y1c * TW + xe));
        float e1 = odd ? __ldg(pl + y1c * TW + x1c) : 0.0f;
        float c10 = odd ? a1.y : a1.x;
        float c11 = odd ? e1   : a1.y;

        float acc = c00 * w00 + c01 * w01 + c10 * w10 + c11 * w11;
        if (c == 0) r = acc; else if (c == 1) g = acc; else bl = acc;
    }
    return make_float3(r, g, bl);
}

// Phase 1: build the (b, i, vi, ui) -> rgb SoA table. 4 entries per thread
// (grid-strided by quarter) so the gathers overlap.
#define BT_THREADS 256
#define BT_QUARTER (NB * TBL_PER_B / 4)      // 62500
__global__ void __launch_bounds__(BT_THREADS)
build_table(const float* __restrict__ tex, const float* __restrict__ lut) {
    int t = blockIdx.x * blockDim.x + threadIdx.x;
    if (t >= BT_QUARTER) return;

    int eb[4], er[4];
    float us[4], vs[4];
#pragma unroll
    for (int h = 0; h < 4; h++) {
        int e = t + h * BT_QUARTER;
        int b  = e / TBL_PER_B;
        int r  = e - b * TBL_PER_B;
        int i  = r / (TD * TD);
        int r2 = r - i * (TD * TD);
        int vi = r2 / TD;
        int ui = r2 - vi * TD;
        int lo = ((i * LD + vi) * LD + ui) * 2;
        us[h] = __ldg(lut + lo);
        vs[h] = __ldg(lut + lo + 1);
        eb[h] = b; er[h] = r;
    }
#pragma unroll
    for (int h = 0; h < 4; h++) {
        float3 c = sample_tex_pair(tex, eb[h], us[h], vs[h]);
        int o = eb[h] * PSTRIDE + er[h];
        g_tab[0][o] = c.x;
        g_tab[1][o] = c.y;
        g_tab[2][o] = c.z;
    }
}

// Phase 2: streaming pass with fp32 table slice staged in shared memory.
// 187.5 KB smem/CTA -> 1 CTA/SM, 144 CTAs = one full wave.
// Byte-identical structure to the proven R11 kernel.
__global__ void __launch_bounds__(MAP_THREADS, 1)
map_pixels(const float* __restrict__ tex,
           const int* __restrict__ iuv,
           const float* __restrict__ lut,
           float* __restrict__ out) {
    extern __shared__ float smem[];
    float* sr = smem;
    float* sg = smem + PSTRIDE;
    float* sb = smem + 2 * PSTRIDE;

    int b   = blockIdx.x / CTAS_PER_B;
    int sub = blockIdx.x - b * CTAS_PER_B;
    int tid = threadIdx.x;

    // Stage this batch's table slice into smem (float4 bulk copy).
#pragma unroll
    for (int c = 0; c < 3; c++) {
        const float4* src = (const float4*)&g_tab[c][b * PSTRIDE];
        float4* dst = (float4*)(smem + c * PSTRIDE);
        for (int t = tid; t < PSTRIDE / 4; t += MAP_THREADS)
            dst[t] = src[t];
    }
    __syncthreads();

    const int* __restrict__ ib = iuv + (size_t)b * OUT_IMG;
    float* __restrict__ ob = out + (size_t)b * OUT_IMG;
    const int q0 = sub * QUADS_PER_CTA;

    // 2 quads (8 pixels) per iteration: 6 front-batched int4 loads for MLP.
#pragma unroll
    for (int j = 0; j < QUADS_PER_CTA / (2 * MAP_THREADS); j++) {
        int qa = q0 + j * (2 * MAP_THREADS) + tid;
        int qb = qa + MAP_THREADS;

        int4 iA = ((const int4*)(ib))[qa];
        int4 iB = ((const int4*)(ib))[qb];
        int4 uA = ((const int4*)(ib + OUT_PLANE))[qa];
        int4 uB = ((const int4*)(ib + OUT_PLANE))[qb];
        int4 vA = ((const int4*)(ib + 2 * OUT_PLANE))[qa];
        int4 vB = ((const int4*)(ib + 2 * OUT_PLANE))[qb];

        int ia[8] = {iA.x, iA.y, iA.z, iA.w, iB.x, iB.y, iB.z, iB.w};
        int ua[8] = {uA.x, uA.y, uA.z, uA.w, uB.x, uB.y, uB.z, uB.w};
        int va[8] = {vA.x, vA.y, vA.z, vA.w, vB.x, vB.y, vB.z, vB.w};

        // Compute all 8 table indices + a combined fast-path predicate.
        // For int32 inputs, rint(clip(ua/255,0,1)*255) == clamp(ua,0,255).
        int idx[8];
        bool fast = true;
#pragma unroll
        for (int k = 0; k < 8; k++) {
            int i  = min(max(ia[k], 0), NI - 1);
            int ui = min(max(ua[k], 0), LD - 1);
            int vi = min(max(va[k], 0), LD - 1);
            fast = fast & (ui < TD) & (vi < TD);
            int uic = min(ui, TD - 1);
            int vic = min(vi, TD - 1);
            idx[k] = (i * TD + vic) * TD + uic;
        }

        float rr[8], gg[8], bb[8];
        if (fast) {
            // Straight-line: 24 independent LDS, batched by ptxas.
#pragma unroll
            for (int k = 0; k < 8; k++) rr[k] = sr[idx[k]];
#pragma unroll
            for (int k = 0; k < 8; k++) gg[k] = sg[idx[k]];
#pragma unroll
            for (int k = 0; k < 8; k++) bb[k] = sb[idx[k]];
        } else {
            // Cold mixed path: per-pixel, exact reference semantics.
#pragma unroll
            for (int k = 0; k < 8; k++) {
                int i  = min(max(ia[k], 0), NI - 1);
                int ui = min(max(ua[k], 0), LD - 1);
                int vi = min(max(va[k], 0), LD - 1);
                if (ui < TD && vi < TD) {
                    int id = (i * TD + vi) * TD + ui;
                    rr[k] = sr[id]; gg[k] = sg[id]; bb[k] = sb[id];
                } else {
                    int lo = ((i * LD + vi) * LD + ui) * 2;
                    float3 c = sample_tex_branchy(tex, b, lut[lo], lut[lo + 1]);
                    rr[k] = c.x; gg[k] = c.y; bb[k] = c.z;
                }
            }
        }

        ((float4*)(ob))[qa]                 = make_float4(rr[0], rr[1], rr[2], rr[3]);
        ((float4*)(ob))[qb]                 = make_float4(rr[4], rr[5], rr[6], rr[7]);
        ((float4*)(ob + OUT_PLANE))[qa]     = make_float4(gg[0], gg[1], gg[2], gg[3]);
        ((float4*)(ob + OUT_PLANE))[qb]     = make_float4(gg[4], gg[5], gg[6], gg[7]);
        ((float4*)(ob + 2 * OUT_PLANE))[qa] = make_float4(bb[0], bb[1], bb[2], bb[3]);
        ((float4*)(ob + 2 * OUT_PLANE))[qb] = make_float4(bb[4], bb[5], bb[6], bb[7]);
    }
}

extern "C" void kernel_launch(void* const* d_in, const int* in_sizes, int n_in,
                              void* d_out, int out_size) {
    const float* tex = (const float*)d_in[0];   // [16,3,512,512] f32
    const int*   iuv = (const int*)d_in[1];     // [16,3,768,768] i32
    const float* lut = (const float*)d_in[2];   // [25,256,256,2] f32
    float* out = (float*)d_out;                 // [16,3,768,768] f32

    build_table<<<(BT_QUARTER + BT_THREADS - 1) / BT_THREADS, BT_THREADS>>>(tex, lut);

    {
        const int smem_bytes = 3 * PSTRIDE * (int)sizeof(float);  // 187,536 B
        // cudaFuncSetAttribute is host-side (not a stream op): capture-safe.
        cudaFuncSetAttribute(map_pixels,
                             cudaFuncAttributeMaxDynamicSharedMemorySize,
                             smem_bytes);
        map_pixels<<<NB * CTAS_PER_B, MAP_THREADS, smem_bytes>>>(tex, iuv, lut, out);
    }
}

// round 14
// speedup vs baseline: 1.4241x; 1.0466x over previous
#include <cuda_runtime.h>

// Problem shapes (fixed by the dataset)
#define NB 16        // batch
#define NC 3         // channels
#define TH 512       // tex H
#define TW 512       // tex W
#define OH 768       // out H
#define OW 768       // out W
#define NI 25        // lut dim 0 (part index)
#define LD 256       // lut dims 1,2
#define TD 25        // table coverage for vi/ui (data has values in [0,25))

#define TEX_PLANE (TH*TW)          // 262144
#define TEX_IMG   (NC*TEX_PLANE)   // 786432
#define OUT_PLANE (OH*OW)          // 589824
#define OUT_IMG   (NC*OUT_PLANE)   // 1769472
#define TBL_PER_B (NI*TD*TD)       // 15625
#define PSTRIDE   15628            // TBL_PER_B padded to /4 for float4 copies

#define CTAS_PER_B 9               // 589824 = 9 * 65536 -> 144 CTAs = one wave
#define QUADS_PER_CTA 16384        // 65536 pixels / 4
#define MAP_THREADS 1024

// Precomputed sample table, SoA: 3 planes of [B][PSTRIDE] floats (~3 MB, L2-resident)
__device__ float g_tab[3][NB * PSTRIDE];

// ---------------------------------------------------------------------------
// Variant A (map_pixels' fallback — branchy, exact R4/R9/R11 form):
// bilinear grid-sample matching torch grid_sample (bilinear, zeros,
// align_corners=True).
__device__ __forceinline__ float3 sample_tex_branchy(const float* __restrict__ tex,
                                                     int b, float us, float vs) {
    float uI = us * 2.0f - 1.0f;
    float vI = (1.0f - vs) * 2.0f - 1.0f;
    float x = (uI + 1.0f) * 0.5f * (float)(TW - 1);
    float y = (vI + 1.0f) * 0.5f * (float)(TH - 1);
    float x0f = floorf(x);
    float y0f = floorf(y);
    float wx = x - x0f;
    float wy = y - y0f;
    int x0 = (int)x0f;
    int y0 = (int)y0f;

    const float* __restrict__ base = tex + (size_t)b * TEX_IMG;
    float r = 0.0f, g = 0.0f, bl = 0.0f;
#pragma unroll
    for (int dy = 0; dy < 2; dy++) {
#pragma unroll
        for (int dx = 0; dx < 2; dx++) {
            int xx = x0 + dx;
            int yy = y0 + dy;
            bool valid = (xx >= 0) & (xx < TW) & (yy >= 0) & (yy < TH);
            float w = (dy ? wy : (1.0f - wy)) * (dx ? wx : (1.0f - wx));
            if (valid) {
                int off = yy * TW + xx;
                r  += __ldg(base + off) * w;
                g  += __ldg(base + TEX_PLANE + off) * w;
                bl += __ldg(base + 2 * TEX_PLANE + off) * w;
            }
        }
    }
    return make_float3(r, g, bl);
}

// Phase 1: build the (b, i, vi, ui) -> rgb SoA table.
// Decomposition: ONE CORNER PER LANE (4 lanes per entry, 8 entries per warp).
// Lanes 2k/2k+1 are x-adjacent corners of the same entry and usually share a
// 128B line, halving L1 wavefronts per gather vs entry-per-thread. The 4
// partial weighted corners are combined with two shfl butterflies.
#define BT_THREADS 256
#define BT_LANES (NB * TBL_PER_B * 4)        // 1,000,000
__global__ void __launch_bounds__(BT_THREADS)
build_table(const float* __restrict__ tex, const float* __restrict__ lut) {
    int t = blockIdx.x * blockDim.x + threadIdx.x;
    int e = t >> 2;                 // entry id
    int k = t & 3;                  // corner id: dx = k&1, dy = k>>1
    if (e >= NB * TBL_PER_B) return;

    int b  = e / TBL_PER_B;
    int r  = e - b * TBL_PER_B;
    int i  = r / (TD * TD);
    int r2 = r - i * (TD * TD);
    int vi = r2 / TD;
    int ui = r2 - vi * TD;

    int lo = ((i * LD + vi) * LD + ui) * 2;
    float us = __ldg(lut + lo);
    float vs = __ldg(lut + lo + 1);

    // grid coords (reference arithmetic order)
    float uI = us * 2.0f - 1.0f;
    float vI = (1.0f - vs) * 2.0f - 1.0f;
    float x = (uI + 1.0f) * 0.5f * (float)(TW - 1);
    float y = (vI + 1.0f) * 0.5f * (float)(TH - 1);
    float x0f = floorf(x);
    float y0f = floorf(y);
    float wx = x - x0f;
    float wy = y - y0f;
    int x0 = (int)x0f;
    int y0 = (int)y0f;

    int dx = k & 1;
    int dy = k >> 1;
    int xx = x0 + dx;
    int yy = y0 + dy;
    bool valid = (xx >= 0) & (xx < TW) & (yy >= 0) & (yy < TH);
    float w = (dy ? wy : (1.0f - wy)) * (dx ? wx : (1.0f - wx));
    w = valid ? w : 0.0f;
    int off = min(max(yy, 0), TH - 1) * TW + min(max(xx, 0), TW - 1);

    const float* __restrict__ base = tex + (size_t)b * TEX_IMG;
    float cr = __ldg(base + off) * w;
    float cg = __ldg(base + TEX_PLANE + off) * w;
    float cb = __ldg(base + 2 * TEX_PLANE + off) * w;

    // Reduce the 4 corners within each lane quad.
    cr += __shfl_xor_sync(0xFFFFFFFFu, cr, 1);
    cg += __shfl_xor_sync(0xFFFFFFFFu, cg, 1);
    cb += __shfl_xor_sync(0xFFFFFFFFu, cb, 1);
    cr += __shfl_xor_sync(0xFFFFFFFFu, cr, 2);
    cg += __shfl_xor_sync(0xFFFFFFFFu, cg, 2);
    cb += __shfl_xor_sync(0xFFFFFFFFu, cb, 2);

    if (k == 0) {
        int o = b * PSTRIDE + r;
        g_tab[0][o] = cr;
        g_tab[1][o] = cg;
        g_tab[2][o] = cb;
    }
}

// Phase 2: streaming pass with fp32 table slice staged in shared memory.
// 187.5 KB smem/CTA -> 1 CTA/SM, 144 CTAs = one full wave.
// Byte-identical structure to the proven R11 kernel.
__global__ void __launch_bounds__(MAP_THREADS, 1)
map_pixels(const float* __restrict__ tex,
           const int* __restrict__ iuv,
           const float* __restrict__ lut,
           float* __restrict__ out) {
    extern __shared__ float smem[];
    float* sr = smem;
    float* sg = smem + PSTRIDE;
    float* sb = smem + 2 * PSTRIDE;

    int b   = blockIdx.x / CTAS_PER_B;
    int sub = blockIdx.x - b * CTAS_PER_B;
    int tid = threadIdx.x;

    // Stage this batch's table slice into smem (float4 bulk copy).
#pragma unroll
    for (int c = 0; c < 3; c++) {
        const float4* src = (const float4*)&g_tab[c][b * PSTRIDE];
        float4* dst = (float4*)(smem + c * PSTRIDE);
        for (int t = tid; t < PSTRIDE / 4; t += MAP_THREADS)
            dst[t] = src[t];
    }
    __syncthreads();

    const int* __restrict__ ib = iuv + (size_t)b * OUT_IMG;
    float* __restrict__ ob = out + (size_t)b * OUT_IMG;
    const int q0 = sub * QUADS_PER_CTA;

    // 2 quads (8 pixels) per iteration: 6 front-batched int4 loads for MLP.
#pragma unroll
    for (int j = 0; j < QUADS_PER_CTA / (2 * MAP_THREADS); j++) {
        int qa = q0 + j * (2 * MAP_THREADS) + tid;
        int qb = qa + MAP_THREADS;

        int4 iA = ((const int4*)(ib))[qa];
        int4 iB = ((const int4*)(ib))[qb];
        int4 uA = ((const int4*)(ib + OUT_PLANE))[qa];
        int4 uB = ((const int4*)(ib + OUT_PLANE))[qb];
        int4 vA = ((const int4*)(ib + 2 * OUT_PLANE))[qa];
        int4 vB = ((const int4*)(ib + 2 * OUT_PLANE))[qb];

        int ia[8] = {iA.x, iA.y, iA.z, iA.w, iB.x, iB.y, iB.z, iB.w};
        int ua[8] = {uA.x, uA.y, uA.z, uA.w, uB.x, uB.y, uB.z, uB.w};
        int va[8] = {vA.x, vA.y, vA.z, vA.w, vB.x, vB.y, vB.z, vB.w};

        // Compute all 8 table indices + a combined fast-path predicate.
        // For int32 inputs, rint(clip(ua/255,0,1)*255) == clamp(ua,0,255).
        int idx[8];
        bool fast = true;
#pragma unroll
        for (int k = 0; k < 8; k++) {
            int i  = min(max(ia[k], 0), NI - 1);
            int ui = min(max(ua[k], 0), LD - 1);
            int vi = min(max(va[k], 0), LD - 1);
            fast = fast & (ui < TD) & (vi < TD);
            int uic = min(ui, TD - 1);
            int vic = min(vi, TD - 1);
            idx[k] = (i * TD + vic) * TD + uic;
        }

        float rr[8], gg[8], bb[8];
        if (fast) {
            // Straight-line: 24 independent LDS, batched by ptxas.
#pragma unroll
            for (int k = 0; k < 8; k++) rr[k] = sr[idx[k]];
#pragma unroll
            for (int k = 0; k < 8; k++) gg[k] = sg[idx[k]];
#pragma unroll
            for (int k = 0; k < 8; k++) bb[k] = sb[idx[k]];
        } else {
            // Cold mixed path: per-pixel, exact reference semantics.
#pragma unroll
            for (int k = 0; k < 8; k++) {
                int i  = min(max(ia[k], 0), NI - 1);
                int ui = min(max(ua[k], 0), LD - 1);
                int vi = min(max(va[k], 0), LD - 1);
                if (ui < TD && vi < TD) {
                    int id = (i * TD + vi) * TD + ui;
                    rr[k] = sr[id]; gg[k] = sg[id]; bb[k] = sb[id];
                } else {
                    int lo = ((i * LD + vi) * LD + ui) * 2;
                    float3 c = sample_tex_branchy(tex, b, lut[lo], lut[lo + 1]);
                    rr[k] = c.x; gg[k] = c.y; bb[k] = c.z;
                }
            }
        }

        ((float4*)(ob))[qa]                 = make_float4(rr[0], rr[1], rr[2], rr[3]);
        ((float4*)(ob))[qb]                 = make_float4(rr[4], rr[5], rr[6], rr[7]);
        ((float4*)(ob + OUT_PLANE))[qa]     = make_float4(gg[0], gg[1], gg[2], gg[3]);
        ((float4*)(ob + OUT_PLANE))[qb]     = make_float4(gg[4], gg[5], gg[6], gg[7]);
        ((float4*)(ob + 2 * OUT_PLANE))[qa] = make_float4(bb[0], bb[1], bb[2], bb[3]);
        ((float4*)(ob + 2 * OUT_PLANE))[qb] = make_float4(bb[4], bb[5], bb[6], bb[7]);
    }
}

extern "C" void kernel_launch(void* const* d_in, const int* in_sizes, int n_in,
                              void* d_out, int out_size) {
    const float* tex = (const float*)d_in[0];   // [16,3,512,512] f32
    const int*   iuv = (const int*)d_in[1];     // [16,3,768,768] i32
    const float* lut = (const float*)d_in[2];   // [25,256,256,2] f32
    float* out = (float*)d_out;                 // [16,3,768,768] f32

    build_table<<<(BT_LANES + BT_THREADS - 1) / BT_THREADS, BT_THREADS>>>(tex, lut);

    {
        const int smem_bytes = 3 * PSTRIDE * (int)sizeof(float);  // 187,536 B
        // cudaFuncSetAttribute is host-side (not a stream op): capture-safe.
        cudaFuncSetAttribute(map_pixels,
                             cudaFuncAttributeMaxDynamicSharedMemorySize,
                             smem_bytes);
        map_pixels<<<NB * CTAS_PER_B, MAP_THREADS, smem_bytes>>>(tex, iuv, lut, out);
    }
}

// round 16
// speedup vs baseline: 1.4258x; 1.0012x over previous
#include <cuda_runtime.h>

// Problem shapes (fixed by the dataset)
#define NB 16        // batch
#define NC 3         // channels
#define TH 512       // tex H
#define TW 512       // tex W
#define OH 768       // out H
#define OW 768       // out W
#define NI 25        // lut dim 0 (part index)
#define LD 256       // lut dims 1,2
#define TD 25        // table coverage for vi/ui (data has values in [0,25))

#define TEX_PLANE (TH*TW)          // 262144
#define TEX_IMG   (NC*TEX_PLANE)   // 786432
#define OUT_PLANE (OH*OW)          // 589824
#define OUT_IMG   (NC*OUT_PLANE)   // 1769472
#define TBL_PER_B (NI*TD*TD)       // 15625
#define PST_RG    15626            // float2 rg plane stride (even; 125008 B)
#define PST_B     15628            // float b plane stride (/4; 62512 B)

#define CTAS_PER_B 9               // 589824 = 9 * 65536 -> 144 CTAs = one wave
#define QUADS_PER_CTA 16384        // 65536 pixels / 4
#define MAP_THREADS 1024

// Precomputed sample table: float2 rg plane + float b plane (~3 MB, L2-resident)
__device__ float2 g_tab_rg[NB * PST_RG];
__device__ float  g_tab_b [NB * PST_B];

// ---------------------------------------------------------------------------
// Variant A (map_pixels' fallback — branchy, exact R4/R9/R11 form):
// bilinear grid-sample matching torch grid_sample (bilinear, zeros,
// align_corners=True).
__device__ __forceinline__ float3 sample_tex_branchy(const float* __restrict__ tex,
                                                     int b, float us, float vs) {
    float uI = us * 2.0f - 1.0f;
    float vI = (1.0f - vs) * 2.0f - 1.0f;
    float x = (uI + 1.0f) * 0.5f * (float)(TW - 1);
    float y = (vI + 1.0f) * 0.5f * (float)(TH - 1);
    float x0f = floorf(x);
    float y0f = floorf(y);
    float wx = x - x0f;
    float wy = y - y0f;
    int x0 = (int)x0f;
    int y0 = (int)y0f;

    const float* __restrict__ base = tex + (size_t)b * TEX_IMG;
    float r = 0.0f, g = 0.0f, bl = 0.0f;
#pragma unroll
    for (int dy = 0; dy < 2; dy++) {
#pragma unroll
        for (int dx = 0; dx < 2; dx++) {
            int xx = x0 + dx;
            int yy = y0 + dy;
            bool valid = (xx >= 0) & (xx < TW) & (yy >= 0) & (yy < TH);
            float w = (dy ? wy : (1.0f - wy)) * (dx ? wx : (1.0f - wx));
            if (valid) {
                int off = yy * TW + xx;
                r  += __ldg(base + off) * w;
                g  += __ldg(base + TEX_PLANE + off) * w;
                bl += __ldg(base + 2 * TEX_PLANE + off) * w;
            }
        }
    }
    return make_float3(r, g, bl);
}

// Phase 1: build the (b, i, vi, ui) -> rgb table.
// Decomposition: ONE CORNER PER LANE (4 lanes per entry, 8 entries per warp).
// Lanes 2k/2k+1 are x-adjacent corners of the same entry and usually share a
// 128B line, halving L1 wavefronts per gather vs entry-per-thread. The 4
// partial weighted corners are combined with two shfl butterflies.
#define BT_THREADS 256
#define BT_LANES (NB * TBL_PER_B * 4)        // 1,000,000
__global__ void __launch_bounds__(BT_THREADS)
build_table(const float* __restrict__ tex, const float* __restrict__ lut) {
    int t = blockIdx.x * blockDim.x + threadIdx.x;
    int e = t >> 2;                 // entry id
    int k = t & 3;                  // corner id: dx = k&1, dy = k>>1
    if (e >= NB * TBL_PER_B) return;

    int b  = e / TBL_PER_B;
    int r  = e - b * TBL_PER_B;
    int i  = r / (TD * TD);
    int r2 = r - i * (TD * TD);
    int vi = r2 / TD;
    int ui = r2 - vi * TD;

    int lo = ((i * LD + vi) * LD + ui) * 2;
    float us = __ldg(lut + lo);
    float vs = __ldg(lut + lo + 1);

    // grid coords (reference arithmetic order)
    float uI = us * 2.0f - 1.0f;
    float vI = (1.0f - vs) * 2.0f - 1.0f;
    float x = (uI + 1.0f) * 0.5f * (float)(TW - 1);
    float y = (vI + 1.0f) * 0.5f * (float)(TH - 1);
    float x0f = floorf(x);
    float y0f = floorf(y);
    float wx = x - x0f;
    float wy = y - y0f;
    int x0 = (int)x0f;
    int y0 = (int)y0f;

    int dx = k & 1;
    int dy = k >> 1;
    int xx = x0 + dx;
    int yy = y0 + dy;
    bool valid = (xx >= 0) & (xx < TW) & (yy >= 0) & (yy < TH);
    float w = (dy ? wy : (1.0f - wy)) * (dx ? wx : (1.0f - wx));
    w = valid ? w : 0.0f;
    int off = min(max(yy, 0), TH - 1) * TW + min(max(xx, 0), TW - 1);

    const float* __restrict__ base = tex + (size_t)b * TEX_IMG;
    float cr = __ldg(base + off) * w;
    float cg = __ldg(base + TEX_PLANE + off) * w;
    float cb = __ldg(base + 2 * TEX_PLANE + off) * w;

    // Reduce the 4 corners within each lane quad.
    cr += __shfl_xor_sync(0xFFFFFFFFu, cr, 1);
    cg += __shfl_xor_sync(0xFFFFFFFFu, cg, 1);
    cb += __shfl_xor_sync(0xFFFFFFFFu, cb, 1);
    cr += __shfl_xor_sync(0xFFFFFFFFu, cr, 2);
    cg += __shfl_xor_sync(0xFFFFFFFFu, cg, 2);
    cb += __shfl_xor_sync(0xFFFFFFFFu, cb, 2);

    if (k == 0) {
        g_tab_rg[b * PST_RG + r] = make_float2(cr, cg);
        g_tab_b [b * PST_B  + r] = cb;
    }
}

// Phase 2: streaming pass with table slice staged in shared memory.
// ~187.5 KB smem/CTA -> 1 CTA/SM, 144 CTAs = one full wave.
// Identical loop structure to R11/R14; only the smem table layout changed:
// 2 LDS per pixel (LDS.64 rg + LDS.32 b) instead of 3 LDS.32.
__global__ void __launch_bounds__(MAP_THREADS, 1)
map_pixels(const float* __restrict__ tex,
           const int* __restrict__ iuv,
           const float* __restrict__ lut,
           float* __restrict__ out) {
    extern __shared__ char smem[];
    float2* srg = (float2*)smem;                         // 15626*8 = 125008 B
    float*  sb  = (float*)(smem + PST_RG * 8);           // 15628*4 =  62512 B

    int b   = blockIdx.x / CTAS_PER_B;
    int sub = blockIdx.x - b * CTAS_PER_B;
    int tid = threadIdx.x;

    // Stage this batch's table slice into smem (float4 bulk copy).
    {
        const float4* src = (const float4*)&g_tab_rg[b * PST_RG];
        float4* dst = (float4*)srg;
        for (int t = tid; t < (PST_RG * 8) / 16; t += MAP_THREADS)
            dst[t] = src[t];
        const float4* src2 = (const float4*)&g_tab_b[b * PST_B];
        float4* dst2 = (float4*)sb;
        for (int t = tid; t < (PST_B * 4) / 16; t += MAP_THREADS)
            dst2[t] = src2[t];
    }
    __syncthreads();

    const int* __restrict__ ib = iuv + (size_t)b * OUT_IMG;
    float* __restrict__ ob = out + (size_t)b * OUT_IMG;
    const int q0 = sub * QUADS_PER_CTA;

    // 2 quads (8 pixels) per iteration: 6 front-batched int4 loads for MLP.
#pragma unroll
    for (int j = 0; j < QUADS_PER_CTA / (2 * MAP_THREADS); j++) {
        int qa = q0 + j * (2 * MAP_THREADS) + tid;
        int qb = qa + MAP_THREADS;

        int4 iA = ((const int4*)(ib))[qa];
        int4 iB = ((const int4*)(ib))[qb];
        int4 uA = ((const int4*)(ib + OUT_PLANE))[qa];
        int4 uB = ((const int4*)(ib + OUT_PLANE))[qb];
        int4 vA = ((const int4*)(ib + 2 * OUT_PLANE))[qa];
        int4 vB = ((const int4*)(ib + 2 * OUT_PLANE))[qb];

        int ia[8] = {iA.x, iA.y, iA.z, iA.w, iB.x, iB.y, iB.z, iB.w};
        int ua[8] = {uA.x, uA.y, uA.z, uA.w, uB.x, uB.y, uB.z, uB.w};
        int va[8] = {vA.x, vA.y, vA.z, vA.w, vB.x, vB.y, vB.z, vB.w};

        // Compute all 8 table indices + a combined fast-path predicate.
        // For int32 inputs, rint(clip(ua/255,0,1)*255) == clamp(ua,0,255).
        int idx[8];
        bool fast = true;
#pragma unroll
        for (int k = 0; k < 8; k++) {
            int i  = min(max(ia[k], 0), NI - 1);
            int ui = min(max(ua[k], 0), LD - 1);
            int vi = min(max(va[k], 0), LD - 1);
            fast = fast & (ui < TD) & (vi < TD);
            int uic = min(ui, TD - 1);
            int vic = min(vi, TD - 1);
            idx[k] = (i * TD + vic) * TD + uic;
        }

        float rr[8], gg[8], bb[8];
        if (fast) {
            // Straight-line: 16 independent LDS (8x LDS.64 + 8x LDS.32).
            float2 rg[8];
#pragma unroll
            for (int k = 0; k < 8; k++) rg[k] = srg[idx[k]];
#pragma unroll
            for (int k = 0; k < 8; k++) bb[k] = sb[idx[k]];
#pragma unroll
            for (int k = 0; k < 8; k++) { rr[k] = rg[k].x; gg[k] = rg[k].y; }
        } else {
            // Cold mixed path: per-pixel, exact reference semantics.
#pragma unroll
            for (int k = 0; k < 8; k++) {
                int i  = min(max(ia[k], 0), NI - 1);
                int ui = min(max(ua[k], 0), LD - 1);
                int vi = min(max(va[k], 0), LD - 1);
                if (ui < TD && vi < TD) {
                    int id = (i * TD + vi) * TD + ui;
                    float2 rg = srg[id];
                    rr[k] = rg.x; gg[k] = rg.y; bb[k] = sb[id];
                } else {
                    int lo = ((i * LD + vi) * LD + ui) * 2;
                    float3 c = sample_tex_branchy(tex, b, lut[lo], lut[lo + 1]);
                    rr[k] = c.x; gg[k] = c.y; bb[k] = c.z;
                }
            }
        }

        ((float4*)(ob))[qa]                 = make_float4(rr[0], rr[1], rr[2], rr[3]);
        ((float4*)(ob))[qb]                 = make_float4(rr[4], rr[5], rr[6], rr[7]);
        ((float4*)(ob + OUT_PLANE))[qa]     = make_float4(gg[0], gg[1], gg[2], gg[3]);
        ((float4*)(ob + OUT_PLANE))[qb]     = make_float4(gg[4], gg[5], gg[6], gg[7]);
        ((float4*)(ob + 2 * OUT_PLANE))[qa] = make_float4(bb[0], bb[1], bb[2], bb[3]);
        ((float4*)(ob + 2 * OUT_PLANE))[qb] = make_float4(bb[4], bb[5], bb[6], bb[7]);
    }
}

extern "C" void kernel_launch(void* const* d_in, const int* in_sizes, int n_in,
                              void* d_out, int out_size) {
    const float* tex = (const float*)d_in[0];   // [16,3,512,512] f32
    const int*   iuv = (const int*)d_in[1];     // [16,3,768,768] i32
    const float* lut = (const float*)d_in[2];   // [25,256,256,2] f32
    float* out = (float*)d_out;                 // [16,3,768,768] f32

    build_table<<<(BT_LANES + BT_THREADS - 1) / BT_THREADS, BT_THREADS>>>(tex, lut);

    {
        const int smem_bytes = PST_RG * 8 + PST_B * 4;  // 187,520 B
        // cudaFuncSetAttribute is host-side (not a stream op): capture-safe.
        cudaFuncSetAttribute(map_pixels,
                             cudaFuncAttributeMaxDynamicSharedMemorySize,
                             smem_bytes);
        map_pixels<<<NB * CTAS_PER_B, MAP_THREADS, smem_bytes>>>(tex, iuv, lut, out);
    }
}